// round 4
// baseline (speedup 1.0000x reference)
#include <cuda_runtime.h>
#include <cstdint>
#include <math.h>

// ---------------------------------------------------------------------------
// ClassicalMappedQRNN: B=8192 independent chains, sequential over S=4096.
// Fast path (alpha = beta = pi/2), state G = 4*h_dir (unnormalized), packed:
//   X = (g0, g2), Yn = (-g1, g3)                      [f32x2 pairs]
//   r = cos(phi) = rsqrt(1+x^2)
//   C = 2*sqrt(1+r)   = 2*sqrt2*cos(phi/2)            (v4 = 4*unit v)
//   S = 2*x*r/sqrt(1+r) = 2*sqrt2*sin(phi/2)
//   v4 = (C, -S, S, C),  ||v4|| = 4
//   W = Rz-unscaled(G):  W02 = X+Yn = (w0,w2); W13 = X-Yn = (w1,-w3)
//   G' = K*W + v4,  K = 4/(sqrt2*||G||)  =>  ||K W|| = 4
//   d  = <W, v4> = C*(w0+w3) + S*(w2-w1)
//   K' = rsqrt(4 + 0.25*K*d)            (20-cyc serial core: FFMA + MUFU.RSQ)
// fp32 scalar ops are HALF-RATE (rt_SMSP=2) on sm_103a; f32x2 packed ops give
// 2 lanes per rt-2 issue -> the vector algebra runs at full fp32 rate.
// ---------------------------------------------------------------------------

typedef unsigned long long u64;

__device__ __forceinline__ float rsqa(float x) {
    float y; asm("rsqrt.approx.f32 %0, %1;" : "=f"(y) : "f"(x)); return y;
}
__device__ __forceinline__ u64 pk2(float lo, float hi) {
    u64 r; asm("mov.b64 %0, {%1, %2};" : "=l"(r) : "f"(lo), "f"(hi)); return r;
}
__device__ __forceinline__ void upk2(u64 v, float& lo, float& hi) {
    asm("mov.b64 {%0, %1}, %2;" : "=f"(lo), "=f"(hi) : "l"(v));
}
__device__ __forceinline__ u64 f2fma(u64 a, u64 b, u64 c) {
    u64 r; asm("fma.rn.f32x2 %0, %1, %2, %3;" : "=l"(r) : "l"(a), "l"(b), "l"(c)); return r;
}
__device__ __forceinline__ u64 f2add(u64 a, u64 b) {
    u64 r; asm("add.rn.f32x2 %0, %1, %2;" : "=l"(r) : "l"(a), "l"(b)); return r;
}
__device__ __forceinline__ u64 f2mul(u64 a, u64 b) {
    u64 r; asm("mul.rn.f32x2 %0, %1, %2;" : "=l"(r) : "l"(a), "l"(b)); return r;
}

__device__ __forceinline__ void cp_async16(uint32_t dst_smem, const void* src) {
    asm volatile("cp.async.cg.shared.global [%0], [%1], 16;"
                 :: "r"(dst_smem), "l"(src));
}
__device__ __forceinline__ void cp_commit() { asm volatile("cp.async.commit_group;"); }
template <int N>
__device__ __forceinline__ void cp_wait() {
    asm volatile("cp.async.wait_group %0;" :: "n"(N));
}

#define CHUNK 32                 // steps per smem chunk
#define TPB   64                 // 2 warps -> SMSP 0,1; 1 block/SM
#define ROWF  36                 // padded floats per thread row
#define NBUF  3                  // triple buffer (lookahead crosses chunks)

struct Trig { float C, S; };

__device__ __forceinline__ Trig trig1(float x) {
    float t  = fmaf(x, x, 1.0f);
    float r  = rsqa(t);                   // cos(phi)
    float e  = fmaf(r, 0.25f, 0.25f);     // (1+r)/4
    float q  = rsqa(e);                   // 2/sqrt(1+r)
    float xr = x * r;
    Trig o;
    o.C = fmaf(r, q, q);                  // 2*sqrt(1+r)
    o.S = xr * q;                         // 2*x*r/sqrt(1+r)
    return o;
}

struct State { u64 X, Yn; float K; };

#define GUARD_M 4.000021f        // 4 + eps: keeps m > 0 at exact anti-alignment

__device__ __forceinline__ void stepf(State& s, Trig tg, u64 NEG2) {
    u64 Va  = pk2(tg.C, tg.S);
    u64 Vb  = pk2(tg.S, tg.C);
    u64 W02 = f2add(s.X, s.Yn);                 // (w0, w2)
    u64 W13 = f2fma(s.Yn, NEG2, s.X);           // (w1, -w3)
    float w1, nw3; upk2(W13, w1, nw3);
    u64 Wsw = pk2(nw3, w1);                     // swap(W13)
    u64 PQ  = f2fma(Wsw, NEG2, W02);            // (w0+w3, w2-w1)
    u64 dv  = f2mul(PQ, Va);                    // (P*C, Q*S)
    float dl, dh; upk2(dv, dl, dh);
    float d4 = (dl + dh) * 0.25f;               // <W,v4>/4   (off-chain)
    float K  = s.K;
    float Kn = -K;
    u64 KK   = pk2(K, K);
    u64 KKn  = pk2(Kn, Kn);
    s.X  = f2fma(KK,  W02, Va);                 // (n0, n2)
    s.Yn = f2fma(KKn, W13, Vb);                 // (-n1, n3)
    float m = fmaf(K, d4, GUARD_M);             // 4 + K<W,v4>/4
    s.K = rsqa(m);                              // serial core: FFMA + RSQ
}

__device__ __forceinline__ void renorm(State& s) {
    u64 sq = f2fma(s.X, s.X, f2mul(s.Yn, s.Yn));
    float a, b; upk2(sq, a, b);
    s.K = rsqa(0.125f * (a + b));               // exact 4/(sqrt2*||G||)
}

// One chunk of 32 steps (8 groups of 4), with trig lookahead one group ahead.
// tg[] holds trig for the group about to be processed; on exit it holds trig
// for the NEXT chunk's group 0 (read from sbn).
template <bool FIRST>
__device__ __forceinline__ void proc_chunk(State& s, Trig* tg,
                                           const float* __restrict__ sb,
                                           const float* __restrict__ sbn,
                                           u64 NEG2) {
    #pragma unroll
    for (int g = 0; g < 8; g++) {
        float4 fn = (g < 7) ? *reinterpret_cast<const float4*>(sb + (g + 1) * 4)
                            : *reinterpret_cast<const float4*>(sbn);
        // interleave lookahead trig with the serial core (fills chain stalls)
        Trig t0 = trig1(fn.x);
        if (FIRST && g == 0) {
            s.X  = pk2(tg[0].C, tg[0].S);       // G = v4 (hidden0 = 0)
            s.Yn = pk2(tg[0].S, tg[0].C);
            s.K  = 0.70710678f;                 // 4/(sqrt2*4)
        } else {
            stepf(s, tg[0], NEG2);
        }
        Trig t1 = trig1(fn.y);
        stepf(s, tg[1], NEG2);
        Trig t2 = trig1(fn.z);
        stepf(s, tg[2], NEG2);
        Trig t3 = trig1(fn.w);
        stepf(s, tg[3], NEG2);
        tg[0] = t0; tg[1] = t1; tg[2] = t2; tg[3] = t3;
    }
    renorm(s);                                  // kill approx-rsqrt drift
}

__shared__ float sbuf[NBUF * TPB * ROWF];

__device__ __forceinline__ void issue_chunk(const float* __restrict__ xrow,
                                            int c, int buf, int tid) {
    uint32_t dst = (uint32_t)__cvta_generic_to_shared(
        &sbuf[buf * (TPB * ROWF) + tid * ROWF]);
    const float* src = xrow + c * CHUNK;
    #pragma unroll
    for (int i = 0; i < CHUNK / 4; i++)
        cp_async16(dst + i * 16, src + i * 4);
    cp_commit();
}

__device__ void run_fast(const float* __restrict__ xrow,
                         float* __restrict__ outb, int S, int tid) {
    const u64 NEG2 = pk2(-1.0f, -1.0f);
    const int nch = S / CHUNK;                  // >= 4 guaranteed by caller

    issue_chunk(xrow, 0, 0, tid);
    issue_chunk(xrow, 1, 1, tid);
    issue_chunk(xrow, 2, 2, tid);

    State s;
    Trig tg[4];

    #pragma unroll 1
    for (int c = 0; c < nch; c++) {
        if (c + 2 < nch) cp_wait<1>(); else cp_wait<0>();
        const float* sb  = &sbuf[(c % NBUF) * (TPB * ROWF) + tid * ROWF];
        const float* sbn = (c + 1 < nch)
            ? &sbuf[((c + 1) % NBUF) * (TPB * ROWF) + tid * ROWF] : sb;
        if (c == 0) {
            float4 f0 = *reinterpret_cast<const float4*>(sb);
            tg[0] = trig1(f0.x); tg[1] = trig1(f0.y);
            tg[2] = trig1(f0.z); tg[3] = trig1(f0.w);
            proc_chunk<true>(s, tg, sb, sbn, NEG2);
        } else {
            proc_chunk<false>(s, tg, sb, sbn, NEG2);
        }
        if (c + 3 < nch) issue_chunk(xrow, c + 3, c % NBUF, tid);
    }

    float g0, g2, ng1, g3;
    upk2(s.X, g0, g2);
    upk2(s.Yn, ng1, g3);
    float a01 = g0 * g0 + ng1 * ng1;
    float a23 = g2 * g2 + g3 * g3;
    *outb = (a01 - a23) / (a01 + a23);
}

// Exact-ish scalar fallback (generic alpha/beta or odd shapes).
__device__ void run_simple(const float* __restrict__ xrow, float* __restrict__ outb,
                           int S, float ca, float sa, float cb, float sb) {
    float h0 = 0.f, h1 = 0.f, h2 = 0.f, h3 = 0.f;
    for (int t = 0; t < S; t++) {
        float xv = xrow[t];
        float phi = atanf(xv);
        float c = cosf(0.5f * phi);
        float s = sinf(0.5f * phi);
        float u0 = ca * c + cb * h0 - sb * h1;
        float u1 = -(sa * s) + sb * h0 + cb * h1;
        float u2 = ca * s + cb * h2 + sb * h3;
        float u3 = sa * c - sb * h2 + cb * h3;
        float ss = u0*u0 + u1*u1 + u2*u2 + u3*u3;
        float rn = rsqrtf(ss);
        h0 = u0 * rn; h1 = u1 * rn; h2 = u2 * rn; h3 = u3 * rn;
    }
    *outb = (h0*h0 + h1*h1) - (h2*h2 + h3*h3);
}

__global__ void __launch_bounds__(TPB, 1)
qrnn_kernel(const float* __restrict__ x, const float* __restrict__ pa,
            const float* __restrict__ pb, float* __restrict__ out, int B, int S) {
    int tid = threadIdx.x;
    int b = blockIdx.x * TPB + tid;
    if (b >= B) return;

    float alpha = __ldg(pa);
    float beta  = __ldg(pb);
    const float PIO2 = 1.57079632679489662f;
    bool fast = (fabsf(alpha - PIO2) < 1e-5f) && (fabsf(beta - PIO2) < 1e-5f);

    const float* xrow = x + (size_t)b * (size_t)S;
    float* outb = out + b;

    if (fast && S >= 128 && (S % CHUNK) == 0) {
        run_fast(xrow, outb, S, tid);
    } else {
        float ca = cosf(0.5f * alpha), sa = sinf(0.5f * alpha);
        float cb = cosf(0.5f * beta),  sb = sinf(0.5f * beta);
        run_simple(xrow, outb, S, ca, sa, cb, sb);
    }
}

extern "C" void kernel_launch(void* const* d_in, const int* in_sizes, int n_in,
                              void* d_out, int out_size) {
    const float* x  = (const float*)d_in[0];
    const float* pa = (const float*)d_in[1];
    const float* pb = (const float*)d_in[2];
    float* out = (float*)d_out;

    int B = out_size;                 // 8192
    int S = in_sizes[0] / B;          // 4096

    int grid = (B + TPB - 1) / TPB;   // 128 blocks x 64 threads
    qrnn_kernel<<<grid, TPB>>>(x, pa, pb, out, B, S);
}

// round 5
// speedup vs baseline: 1.0619x; 1.0619x over previous
#include <cuda_runtime.h>
#include <cstdint>
#include <math.h>

// ---------------------------------------------------------------------------
// ClassicalMappedQRNN, fast path alpha=beta=pi/2. B=8192 chains, S=4096.
// State G (norm-tracked, scale 2): X=(g0,g2), Yn=(-g1,g3) packed f32x2.
//   r = cos(phi) = rsqrt(1+x^2)
//   C2 = sqrt(1+r)  = sqrt2*cos(phi/2);  S2 = x*r/sqrt(1+r) = sqrt2*sin(phi/2)
//   v2 = (C2,-S2,S2,C2), ||v2|| = 2
//   W = R(G_prev) unscaled Rz;  G = K2*W + v2,  K2 = sqrt2/||G_prev||
//   K2' = rsq(4 + K2*d),  d = <W, v2>
// KEY RESTRUCTURE (removes the dot product from the recurrence cycle):
//   d_t = K2_{t-2} * u_t + c_t
//   c_t = <R(v2_{t-1}), v2_t> = 2(C2'C2 + S2'S2)            (input-only)
//   u_t = <R^2(G_{t-2}), v2_t> = -2[C2(g1+g2) + S2(g0-g3)]  (2-step slack)
// Critical cycle: FFMA(m) + MUFU.RSQ = 20 cyc/step. fma-pipe issue ~36 cyc
// is the new floor (fp32 scalar rt_SMSP=2; f32x2 packed ops used throughout).
// ---------------------------------------------------------------------------

typedef unsigned long long u64;

__device__ __forceinline__ float rsqa(float x) {
    float y; asm("rsqrt.approx.f32 %0, %1;" : "=f"(y) : "f"(x)); return y;
}
__device__ __forceinline__ u64 pk2(float lo, float hi) {
    u64 r; asm("mov.b64 %0, {%1, %2};" : "=l"(r) : "f"(lo), "f"(hi)); return r;
}
__device__ __forceinline__ void upk2(u64 v, float& lo, float& hi) {
    asm("mov.b64 {%0, %1}, %2;" : "=f"(lo), "=f"(hi) : "l"(v));
}
__device__ __forceinline__ u64 f2fma(u64 a, u64 b, u64 c) {
    u64 r; asm("fma.rn.f32x2 %0, %1, %2, %3;" : "=l"(r) : "l"(a), "l"(b), "l"(c)); return r;
}
__device__ __forceinline__ u64 f2add(u64 a, u64 b) {
    u64 r; asm("add.rn.f32x2 %0, %1, %2;" : "=l"(r) : "l"(a), "l"(b)); return r;
}
__device__ __forceinline__ u64 f2mul(u64 a, u64 b) {
    u64 r; asm("mul.rn.f32x2 %0, %1, %2;" : "=l"(r) : "l"(a), "l"(b)); return r;
}

__device__ __forceinline__ void cp_async16(uint32_t dst_smem, const void* src) {
    asm volatile("cp.async.cg.shared.global [%0], [%1], 16;"
                 :: "r"(dst_smem), "l"(src));
}
__device__ __forceinline__ void cp_commit() { asm volatile("cp.async.commit_group;"); }
template <int N>
__device__ __forceinline__ void cp_wait() {
    asm volatile("cp.async.wait_group %0;" :: "n"(N));
}

#define CHUNK 32
#define TPB   64
#define ROWF  36
#define NBUF  3
#define GUARD4 4.000021f

struct Trig { float C, S; };

__device__ __forceinline__ Trig trig1(float x) {
    float t  = fmaf(x, x, 1.0f);
    float r  = rsqa(t);               // cos(phi)
    float e1 = r + 1.0f;
    float q  = rsqa(e1);              // 1/sqrt(1+r)
    Trig o;
    o.C = e1 * q;                     // sqrt(1+r)      = sqrt2 cos(phi/2)
    o.S = (x * r) * q;                // x r / sqrt(1+r) = sqrt2 sin(phi/2)
    return o;
}

struct St {
    u64  X, Yn;          // state G_{t-1}
    u64  Tq0, Tq1;       // T(G_{t-2}), T(G_{t-1});  T = (g0-g3, g2+g1)
    float K2p, K2pp;     // K2_{t-1}, K2_{t-2}
    float twoCp, twoSp;  // 2*trig of step t-1
};

// shared state update tail: compute new state from (C2,S2) and K2p, rotate queues
__device__ __forceinline__ void upd_state(St& s, float C2, float S2, float K2new,
                                          u64 NEG1) {
    u64 Va  = pk2(C2, S2);
    u64 Vb  = pk2(S2, C2);
    u64 W02 = f2add(s.X, s.Yn);                 // (w0, w2)
    u64 W13 = f2fma(s.Yn, NEG1, s.X);           // (w1, -w3)
    u64 KK  = pk2(s.K2p, s.K2p);
    u64 KKn = pk2(-s.K2p, -s.K2p);
    u64 Xn  = f2fma(KK,  W02, Va);              // (n0, n2)
    u64 Ynn = f2fma(KKn, W13, Vb);              // (-n1, n3)
    float ya, yb; upk2(Ynn, ya, yb);
    u64 Ysw = pk2(yb, ya);                      // (n3, -n1)
    u64 Tn  = f2fma(Ysw, NEG1, Xn);             // (n0-n3, n2+n1)
    s.X = Xn; s.Yn = Ynn;
    s.Tq0 = s.Tq1; s.Tq1 = Tn;
    s.K2pp = s.K2p; s.K2p = K2new;
    s.twoCp = C2 + C2; s.twoSp = S2 + S2;
}

// steady-state pipelined step (t >= 2)
__device__ __forceinline__ void pstep(St& s, Trig tg, u64 NEG1) {
    float C2 = tg.C, S2 = tg.S;
    float twoC = C2 + C2, twoS = S2 + S2;
    float c2 = fmaf(s.twoSp, S2, s.twoCp * C2);      // input-only term
    u64 pu = f2mul(s.Tq0, pk2(twoS, twoC));          // from G_{t-2}: big slack
    float pl, ph; upk2(pu, pl, ph);
    float us = pl + ph;                              // = -u_t
    float d2v = fmaf(-s.K2pp, us, c2);               // d_t
    float m  = fmaf(s.K2p, d2v, GUARD4);             // ON CHAIN
    float K2 = rsqa(m);                              // ON CHAIN (20 cyc cycle)
    // state update (uses K2p; off the K cycle)
    u64 Va  = pk2(C2, S2);
    u64 Vb  = pk2(S2, C2);
    u64 W02 = f2add(s.X, s.Yn);
    u64 W13 = f2fma(s.Yn, NEG1, s.X);
    u64 KK  = pk2(s.K2p, s.K2p);
    u64 KKn = pk2(-s.K2p, -s.K2p);
    u64 Xn  = f2fma(KK,  W02, Va);
    u64 Ynn = f2fma(KKn, W13, Vb);
    float ya, yb; upk2(Ynn, ya, yb);
    u64 Ysw = pk2(yb, ya);
    u64 Tn  = f2fma(Ysw, NEG1, Xn);
    s.X = Xn; s.Yn = Ynn;
    s.Tq0 = s.Tq1; s.Tq1 = Tn;
    s.K2pp = s.K2p; s.K2p = K2;
    s.twoCp = twoC; s.twoSp = twoS;
}

// step 0: G0 = v2_0 (hidden = 0), prime the pipeline
__device__ __forceinline__ void init_step(St& s, Trig tg) {
    float C2 = tg.C, S2 = tg.S;
    s.X  = pk2(C2, S2);
    s.Yn = pk2(S2, C2);
    s.K2p  = 0.70710678118654752f;     // sqrt2/||G0||, ||G0|| = 2
    s.K2pp = 0.0f;                     // never used before overwritten
    s.Tq1  = pk2(0.0f, S2 + S2);       // T(G0) = (C2-C2, S2+S2)
    s.Tq0  = s.Tq1;                    // placeholder (overwritten before use)
    s.twoCp = C2 + C2; s.twoSp = S2 + S2;
}

// step 1: direct dot product (no G_{t-2} exists)
__device__ __forceinline__ void direct_step(St& s, Trig tg, u64 NEG1) {
    float C2 = tg.C, S2 = tg.S;
    u64 W02 = f2add(s.X, s.Yn);
    u64 W13 = f2fma(s.Yn, NEG1, s.X);
    float wa, wb; upk2(W13, wa, wb);            // (w1, -w3)
    u64 Wsw = pk2(wb, wa);
    u64 PQ  = f2fma(Wsw, NEG1, W02);            // (w0+w3, w2-w1)
    u64 dv  = f2mul(PQ, pk2(C2, S2));
    float dl, dh; upk2(dv, dl, dh);
    float d2v = dl + dh;
    float m  = fmaf(s.K2p, d2v, GUARD4);
    float K2 = rsqa(m);
    upd_state(s, C2, S2, K2, NEG1);
}

__device__ __forceinline__ void renorm(St& s) {
    u64 sq = f2fma(s.X, s.X, f2mul(s.Yn, s.Yn));
    float a, b; upk2(sq, a, b);
    s.K2p = rsqa(0.5f * (a + b));               // exact sqrt2/||G||
}

template <bool FIRST>
__device__ __forceinline__ void proc_chunk(St& s, Trig* tg,
                                           const float* __restrict__ sb,
                                           const float* __restrict__ sbn,
                                           u64 NEG1) {
    #pragma unroll
    for (int g = 0; g < 8; g++) {
        float4 fn = (g < 7) ? *reinterpret_cast<const float4*>(sb + (g + 1) * 4)
                            : *reinterpret_cast<const float4*>(sbn);
        // lookahead trig interleaved with this group's steps (hides 40-cyc trig lat)
        Trig t0 = trig1(fn.x);
        if (FIRST && g == 0) init_step(s, tg[0]);
        else                 pstep(s, tg[0], NEG1);
        Trig t1 = trig1(fn.y);
        if (FIRST && g == 0) direct_step(s, tg[1], NEG1);
        else                 pstep(s, tg[1], NEG1);
        Trig t2 = trig1(fn.z);
        pstep(s, tg[2], NEG1);
        Trig t3 = trig1(fn.w);
        pstep(s, tg[3], NEG1);
        tg[0] = t0; tg[1] = t1; tg[2] = t2; tg[3] = t3;
    }
    renorm(s);   // exact rescale every 32 steps: kills approx-rsqrt drift
}

__shared__ float sbuf[NBUF * TPB * ROWF];

__device__ __forceinline__ void issue_chunk(const float* __restrict__ xrow,
                                            int c, int buf, int tid) {
    uint32_t dst = (uint32_t)__cvta_generic_to_shared(
        &sbuf[buf * (TPB * ROWF) + tid * ROWF]);
    const float* src = xrow + c * CHUNK;
    #pragma unroll
    for (int i = 0; i < CHUNK / 4; i++)
        cp_async16(dst + i * 16, src + i * 4);
    cp_commit();
}

__device__ void run_fast(const float* __restrict__ xrow,
                         float* __restrict__ outb, int S, int tid) {
    const u64 NEG1 = pk2(-1.0f, -1.0f);
    const int nch = S / CHUNK;                  // >= 4 (caller guarantees)

    issue_chunk(xrow, 0, 0, tid);
    issue_chunk(xrow, 1, 1, tid);
    issue_chunk(xrow, 2, 2, tid);

    St s;
    Trig tg[4];

    #pragma unroll 1
    for (int c = 0; c < nch; c++) {
        if (c + 2 < nch) cp_wait<1>(); else cp_wait<0>();
        const float* sb  = &sbuf[(c % NBUF) * (TPB * ROWF) + tid * ROWF];
        const float* sbn = (c + 1 < nch)
            ? &sbuf[((c + 1) % NBUF) * (TPB * ROWF) + tid * ROWF] : sb;
        if (c == 0) {
            float4 f0 = *reinterpret_cast<const float4*>(sb);
            tg[0] = trig1(f0.x); tg[1] = trig1(f0.y);
            tg[2] = trig1(f0.z); tg[3] = trig1(f0.w);
            proc_chunk<true>(s, tg, sb, sbn, NEG1);
        } else {
            proc_chunk<false>(s, tg, sb, sbn, NEG1);
        }
        if (c + 3 < nch) issue_chunk(xrow, c + 3, c % NBUF, tid);
    }

    float g0, g2, ng1, g3;
    upk2(s.X, g0, g2);
    upk2(s.Yn, ng1, g3);
    float a01 = g0 * g0 + ng1 * ng1;
    float a23 = g2 * g2 + g3 * g3;
    *outb = (a01 - a23) / (a01 + a23);
}

// Generic-angle / odd-shape fallback.
__device__ void run_simple(const float* __restrict__ xrow, float* __restrict__ outb,
                           int S, float ca, float sa, float cb, float sb) {
    float h0 = 0.f, h1 = 0.f, h2 = 0.f, h3 = 0.f;
    for (int t = 0; t < S; t++) {
        float xv = xrow[t];
        float phi = atanf(xv);
        float c = cosf(0.5f * phi);
        float s = sinf(0.5f * phi);
        float u0 = ca * c + cb * h0 - sb * h1;
        float u1 = -(sa * s) + sb * h0 + cb * h1;
        float u2 = ca * s + cb * h2 + sb * h3;
        float u3 = sa * c - sb * h2 + cb * h3;
        float ss = u0*u0 + u1*u1 + u2*u2 + u3*u3;
        float rn = rsqrtf(ss);
        h0 = u0 * rn; h1 = u1 * rn; h2 = u2 * rn; h3 = u3 * rn;
    }
    *outb = (h0*h0 + h1*h1) - (h2*h2 + h3*h3);
}

__global__ void __launch_bounds__(TPB, 1)
qrnn_kernel(const float* __restrict__ x, const float* __restrict__ pa,
            const float* __restrict__ pb, float* __restrict__ out, int B, int S) {
    int tid = threadIdx.x;
    int b = blockIdx.x * TPB + tid;
    if (b >= B) return;

    float alpha = __ldg(pa);
    float beta  = __ldg(pb);
    const float PIO2 = 1.57079632679489662f;
    bool fast = (fabsf(alpha - PIO2) < 1e-5f) && (fabsf(beta - PIO2) < 1e-5f);

    const float* xrow = x + (size_t)b * (size_t)S;
    float* outb = out + b;

    if (fast && S >= 128 && (S % CHUNK) == 0) {
        run_fast(xrow, outb, S, tid);
    } else {
        float ca = cosf(0.5f * alpha), sa = sinf(0.5f * alpha);
        float cb = cosf(0.5f * beta),  sb = sinf(0.5f * beta);
        run_simple(xrow, outb, S, ca, sa, cb, sb);
    }
}

extern "C" void kernel_launch(void* const* d_in, const int* in_sizes, int n_in,
                              void* d_out, int out_size) {
    const float* x  = (const float*)d_in[0];
    const float* pa = (const float*)d_in[1];
    const float* pb = (const float*)d_in[2];
    float* out = (float*)d_out;

    int B = out_size;                 // 8192
    int S = in_sizes[0] / B;          // 4096

    int grid = (B + TPB - 1) / TPB;   // 128 blocks x 64 threads
    qrnn_kernel<<<grid, TPB>>>(x, pa, pb, out, B, S);
}

// round 6
// speedup vs baseline: 1.0925x; 1.0288x over previous
#include <cuda_runtime.h>
#include <cstdint>
#include <math.h>

// ---------------------------------------------------------------------------
// ClassicalMappedQRNN fast path (alpha=beta=pi/2). B=8192 chains, S=4096.
// Per ref step: phi=atan(x); v-embed; h' = Rx e + Rz h; h'/=||h'||.
// Scaled form: v_t=(C,-S,S,C), C=sqrt2*cos(phi/2), S=sqrt2*sin(phi/2), ||v||=2.
//   G_t = K_{t-1} R(G_{t-1}) + v_t,  K = sqrt2/||G||,  R(g)=(g0-g1,g0+g1,g2+g3,g3-g2)
//   K_t = rsq(4 + K_{t-1} d_t),  d_t = <R G_{t-1}, v_t>
// DOUBLE-STEP FUSION: R^2 = 2J, J(g) = (-g1, g0, g3, -g2)  [free permutation]
//   G_{t+1} = 2K_tK_{t-1} J(G_{t-1}) + K_t (P,M,P,M) + v_{t+1},  P=C+S, M=C-S
//   d_t     = C a + S b;  a,b from butterflies of G_{t-1}
//   d_{t+1} = 2[ (C C' + S S') - K_{t-1} e ],  e = C' (g1+g2) + S' (g0-g3)
// Packing U=(g0,g2), V=(g1,g3): J's signs become per-lane constants ->
// state update = 2x FFMA2, no cross-lane movs. Serial chain: fma+rsq = 20cyc.
// We are issue-bound (256 warps on 592 SMSPs); goal is min slots/step.
// ---------------------------------------------------------------------------

typedef unsigned long long u64;

__device__ __forceinline__ float rsqa(float x) {
    float y; asm("rsqrt.approx.f32 %0, %1;" : "=f"(y) : "f"(x)); return y;
}
__device__ __forceinline__ u64 pk2(float lo, float hi) {
    u64 r; asm("mov.b64 %0, {%1, %2};" : "=l"(r) : "f"(lo), "f"(hi)); return r;
}
__device__ __forceinline__ void upk2(u64 v, float& lo, float& hi) {
    asm("mov.b64 {%0, %1}, %2;" : "=f"(lo), "=f"(hi) : "l"(v));
}
__device__ __forceinline__ u64 f2fma(u64 a, u64 b, u64 c) {
    u64 r; asm("fma.rn.f32x2 %0, %1, %2, %3;" : "=l"(r) : "l"(a), "l"(b), "l"(c)); return r;
}
__device__ __forceinline__ u64 f2add(u64 a, u64 b) {
    u64 r; asm("add.rn.f32x2 %0, %1, %2;" : "=l"(r) : "l"(a), "l"(b)); return r;
}
__device__ __forceinline__ u64 f2mul(u64 a, u64 b) {
    u64 r; asm("mul.rn.f32x2 %0, %1, %2;" : "=l"(r) : "l"(a), "l"(b)); return r;
}

__device__ __forceinline__ void cp_async16(uint32_t dst_smem, const void* src) {
    asm volatile("cp.async.cg.shared.global [%0], [%1], 16;"
                 :: "r"(dst_smem), "l"(src));
}
__device__ __forceinline__ void cp_commit() { asm volatile("cp.async.commit_group;"); }
template <int N>
__device__ __forceinline__ void cp_wait() {
    asm volatile("cp.async.wait_group %0;" :: "n"(N));
}

#define CHUNK 32
#define TPB   64
#define ROWF  36
#define NBUF  3
#define GUARD4 4.000021f

// trig for two independent inputs, packed: C=sqrt2*cos(phi/2), S=sqrt2*sin(phi/2)
struct Trig2 { float C0, S0, C1, S1; };

__device__ __forceinline__ Trig2 trig2(float x0, float x1, u64 ONE2) {
    u64 X = pk2(x0, x1);
    u64 T = f2fma(X, X, ONE2);            // 1 + x^2
    float t0, t1; upk2(T, t0, t1);
    float r0 = rsqa(t0), r1 = rsqa(t1);   // cos(phi)
    u64 Rp = pk2(r0, r1);
    u64 E  = f2add(Rp, ONE2);             // 1 + r
    float e0, e1; upk2(E, e0, e1);
    float q0 = rsqa(e0), q1 = rsqa(e1);   // 1/sqrt(1+r)
    u64 Qp = pk2(q0, q1);
    u64 Cp = f2mul(E, Qp);                // sqrt(1+r)        = sqrt2 cos(phi/2)
    u64 XR = f2mul(X, Rp);
    u64 Sp = f2mul(XR, Qp);               // x r / sqrt(1+r)  = sqrt2 sin(phi/2)
    Trig2 o;
    upk2(Cp, o.C0, o.C1);
    upk2(Sp, o.S0, o.S1);
    return o;
}

__device__ __forceinline__ float trig1C(float x, float& S) {
    float t = fmaf(x, x, 1.0f);
    float r = rsqa(t);
    float e = r + 1.0f;
    float q = rsqa(e);
    S = (x * r) * q;
    return e * q;
}

struct St { u64 U, V; float K1; };   // U=(g0,g2), V=(g1,g3), K1 = sqrt2/||G||

// fused double-step: consumes trig of steps t (C,S) and t+1 (C2,S2)
__device__ __forceinline__ void dstep(St& s, float C, float S, float C2, float S2,
                                      u64 NEG1) {
    // ---- dots from state G_{t-1}
    u64 p = f2add(s.U, s.V);              // (g0+g1, g2+g3)
    u64 q = f2fma(s.V, NEG1, s.U);        // (g0-g1, g2-g3)
    float pl, ph; upk2(p, pl, ph);
    float ql, qh; upk2(q, ql, qh);
    float a = ql - qh;                    // g0-g1-g2+g3
    float b = ph - pl;                    // g2+g3-g0-g1
    float d1 = fmaf(S, b, C * a);         // <R G, v_t>
    float m1 = fmaf(s.K1, d1, GUARD4);
    float K2 = rsqa(m1);                  // ---- serial chain
    float u0, u1; upk2(s.U, u0, u1);
    float v0, v1; upk2(s.V, v0, v1);
    float gam = v0 + u1;                  // g1+g2
    float bet = u0 - v1;                  // g0-g3
    float e   = fmaf(S2, bet, C2 * gam);
    float cc  = fmaf(S, S2, C * C2);      // input-only
    float hf  = fmaf(-s.K1, e, cc);       // (CC'+SS') - K1 e
    float K2_2 = K2 + K2;
    float m2  = fmaf(K2_2, hf, GUARD4);
    float K3  = rsqa(m2);                 // ---- serial chain
    // ---- fused state update: G' = KK2 J(G) + K2 (P,M,P,M) + v'
    float KK2 = K2_2 * s.K1;
    float P = C + S, M = C - S;
    float KP = K2 * P, KM = K2 * M;
    u64 RHS1 = pk2(KP + C2, KP + S2);
    u64 RHS2 = pk2(KM - S2, KM + C2);
    u64 SKa  = pk2(-KK2, KK2);
    u64 SKb  = pk2(KK2, -KK2);
    u64 nU = f2fma(s.V, SKa, RHS1);       // (G'0, G'2) = KK2*(-g1, g3) + ...
    u64 nV = f2fma(s.U, SKb, RHS2);       // (G'1, G'3) = KK2*( g0,-g2) + ...
    s.U = nU; s.V = nV; s.K1 = K3;
}

// single plain step (chunk 0 only)
__device__ __forceinline__ void sstep(St& s, float C, float S) {
    float u0, u1; upk2(s.U, u0, u1);
    float v0, v1; upk2(s.V, v0, v1);
    float w0 = u0 - v0, w1 = u0 + v0, w2 = u1 + v1, w3 = v1 - u1;
    float d  = fmaf(S, w2 - w1, C * (w0 + w3));
    float m  = fmaf(s.K1, d, GUARD4);
    float K2 = rsqa(m);
    s.U = pk2(fmaf(s.K1, w0, C), fmaf(s.K1, w2, S));
    s.V = pk2(fmaf(s.K1, w1, -S), fmaf(s.K1, w3, C));
    s.K1 = K2;
}

__device__ __forceinline__ void renorm(St& s) {
    u64 sq = f2fma(s.U, s.U, f2mul(s.V, s.V));
    float a, b; upk2(sq, a, b);
    s.K1 = rsqa(0.5f * (a + b));          // exact sqrt2/||G||
}

// steady chunk: 32 elements = 16 double-steps, trig lookahead one 4-group ahead
__device__ __forceinline__ void proc_chunk(St& s, Trig2* tg,
                                           const float* __restrict__ sb,
                                           const float* __restrict__ sbn,
                                           u64 NEG1, u64 ONE2) {
    #pragma unroll
    for (int g = 0; g < 8; g++) {
        float4 fn = (g < 7) ? *reinterpret_cast<const float4*>(sb + (g + 1) * 4)
                            : *reinterpret_cast<const float4*>(sbn);
        Trig2 n0 = trig2(fn.x, fn.y, ONE2);
        dstep(s, tg[0].C0, tg[0].S0, tg[0].C1, tg[0].S1, NEG1);
        Trig2 n1 = trig2(fn.z, fn.w, ONE2);
        dstep(s, tg[1].C0, tg[1].S0, tg[1].C1, tg[1].S1, NEG1);
        tg[0] = n0; tg[1] = n1;
    }
    renorm(s);
}

__shared__ float sbuf[NBUF * TPB * ROWF];

__device__ __forceinline__ void issue_chunk(const float* __restrict__ xrow,
                                            int c, int buf, int tid) {
    uint32_t dst = (uint32_t)__cvta_generic_to_shared(
        &sbuf[buf * (TPB * ROWF) + tid * ROWF]);
    const float* src = xrow + c * CHUNK;
    #pragma unroll
    for (int i = 0; i < CHUNK / 4; i++)
        cp_async16(dst + i * 16, src + i * 4);
    cp_commit();
}

__device__ void run_fast(const float* __restrict__ xrow,
                         float* __restrict__ outb, int S, int tid) {
    const u64 NEG1 = pk2(-1.0f, -1.0f);
    const u64 ONE2 = pk2(1.0f, 1.0f);
    const int nch = S / CHUNK;                  // >= 4

    issue_chunk(xrow, 0, 0, tid);
    issue_chunk(xrow, 1, 1, tid);
    issue_chunk(xrow, 2, 2, tid);

    const float* sb0 = &sbuf[tid * ROWF];
    cp_wait<1>();                               // chunks 0 and 1 landed

    // ---- chunk 0: plain scalar path (1/128 of work; keeps steady loop aligned)
    St s;
    {
        float Sx, Cx;
        Cx = trig1C(sb0[0], Sx);
        s.U = pk2(Cx, Sx);                      // G0 = v0
        s.V = pk2(-Sx, Cx);
        s.K1 = 0.70710678118654752f;
        #pragma unroll 4
        for (int i = 1; i < CHUNK; i++) {
            Cx = trig1C(sb0[i], Sx);
            sstep(s, Cx, Sx);
        }
        renorm(s);
    }

    // ---- prime lookahead from chunk 1 (landed)
    Trig2 tg[2];
    {
        const float* sb1 = &sbuf[1 * (TPB * ROWF) + tid * ROWF];
        float4 f0 = *reinterpret_cast<const float4*>(sb1);
        tg[0] = trig2(f0.x, f0.y, ONE2);
        tg[1] = trig2(f0.z, f0.w, ONE2);
    }

    #pragma unroll 1
    for (int c = 1; c < nch; c++) {
        if (c + 2 < nch) cp_wait<1>(); else cp_wait<0>();
        const float* sb  = &sbuf[(c % NBUF) * (TPB * ROWF) + tid * ROWF];
        const float* sbn = (c + 1 < nch)
            ? &sbuf[((c + 1) % NBUF) * (TPB * ROWF) + tid * ROWF] : sb;
        proc_chunk(s, tg, sb, sbn, NEG1, ONE2);
        if (c + 3 < nch) issue_chunk(xrow, c + 3, c % NBUF, tid);
    }

    float u0, u1; upk2(s.U, u0, u1);
    float v0, v1; upk2(s.V, v0, v1);
    float a01 = u0 * u0 + v0 * v0;
    float a23 = u1 * u1 + v1 * v1;
    *outb = (a01 - a23) / (a01 + a23);
}

// Generic-angle / odd-shape fallback.
__device__ void run_simple(const float* __restrict__ xrow, float* __restrict__ outb,
                           int S, float ca, float sa, float cb, float sb) {
    float h0 = 0.f, h1 = 0.f, h2 = 0.f, h3 = 0.f;
    for (int t = 0; t < S; t++) {
        float xv = xrow[t];
        float phi = atanf(xv);
        float c = cosf(0.5f * phi);
        float s = sinf(0.5f * phi);
        float u0 = ca * c + cb * h0 - sb * h1;
        float u1 = -(sa * s) + sb * h0 + cb * h1;
        float u2 = ca * s + cb * h2 + sb * h3;
        float u3 = sa * c - sb * h2 + cb * h3;
        float ss = u0*u0 + u1*u1 + u2*u2 + u3*u3;
        float rn = rsqrtf(ss);
        h0 = u0 * rn; h1 = u1 * rn; h2 = u2 * rn; h3 = u3 * rn;
    }
    *outb = (h0*h0 + h1*h1) - (h2*h2 + h3*h3);
}

__global__ void __launch_bounds__(TPB, 1)
qrnn_kernel(const float* __restrict__ x, const float* __restrict__ pa,
            const float* __restrict__ pb, float* __restrict__ out, int B, int S) {
    int tid = threadIdx.x;
    int b = blockIdx.x * TPB + tid;
    if (b >= B) return;

    float alpha = __ldg(pa);
    float beta  = __ldg(pb);
    const float PIO2 = 1.57079632679489662f;
    bool fast = (fabsf(alpha - PIO2) < 1e-5f) && (fabsf(beta - PIO2) < 1e-5f);

    const float* xrow = x + (size_t)b * (size_t)S;
    float* outb = out + b;

    if (fast && S >= 128 && (S % CHUNK) == 0) {
        run_fast(xrow, outb, S, tid);
    } else {
        float ca = cosf(0.5f * alpha), sa = sinf(0.5f * alpha);
        float cb = cosf(0.5f * beta),  sb = sinf(0.5f * beta);
        run_simple(xrow, outb, S, ca, sa, cb, sb);
    }
}

extern "C" void kernel_launch(void* const* d_in, const int* in_sizes, int n_in,
                              void* d_out, int out_size) {
    const float* x  = (const float*)d_in[0];
    const float* pa = (const float*)d_in[1];
    const float* pb = (const float*)d_in[2];
    float* out = (float*)d_out;

    int B = out_size;                 // 8192
    int S = in_sizes[0] / B;          // 4096

    int grid = (B + TPB - 1) / TPB;   // 128 blocks x 64 threads
    qrnn_kernel<<<grid, TPB>>>(x, pa, pb, out, B, S);
}